// round 2
// baseline (speedup 1.0000x reference)
#include <cuda_runtime.h>
#include <cstdint>

// ---------------------------------------------------------------------------
// RNN_64235530879484 : leaky noisy RNN
//   state_new = relu(state) @ (w_hh masked diag) + bias + x@w_ih + SIGMA*noise
//   state'    = 0.8*state + 0.2*state_new
// out[0] = initial_state, out[t+1] = state after step t.  Shapes:
//   inputs [1000,512,13]  initial_state [512,512]  noise [1000,512,512]
//   weight_ih [13,512]    weight_hh [512,512]      bias_h [1,512]
//   out [1001,512,512] fp32
// Strategy R0: single persistent kernel, 128 CTAs (tile 32x64 of the 512x512
// per-step GEMM), global atomic barrier between steps. fp32 exact.
// ---------------------------------------------------------------------------

#define T_STEPS 1000
#define BATCH   512
#define HDIM    512
#define IDIM    13
#define ALPHA_C 0.2f
#define SIGMA_C 0.15811388300841898f   // sqrt(2/0.2)*0.05

#define TILE_M  32
#define TILE_N  64
#define KC      64
#define NTHREADS 256
#define GRID_X  128     // 16 m-tiles * 8 n-tiles

__device__ float    g_wmask[HDIM * HDIM];   // diag-masked w_hh
__device__ unsigned g_bar;                  // global barrier counter (memset per launch)

// ---------------------------------------------------------------------------
__global__ void prep_kernel(const float* __restrict__ w_hh,
                            const float* __restrict__ init_state,
                            float* __restrict__ out)
{
    const int stride = gridDim.x * blockDim.x;
    int idx = blockIdx.x * blockDim.x + threadIdx.x;
    for (int i = idx; i < HDIM * HDIM; i += stride) {
        int k = i >> 9;          // /512
        int j = i & (HDIM - 1);
        g_wmask[i] = (k == j) ? 0.0f : w_hh[i];
    }
    for (int i = idx; i < BATCH * HDIM; i += stride)
        out[i] = init_state[i];
}

// ---------------------------------------------------------------------------
__global__ __launch_bounds__(NTHREADS, 1)
void rnn_kernel(const float* __restrict__ inputs,
                const float* __restrict__ noise,
                const float* __restrict__ w_ih,
                const float* __restrict__ bias,
                float* __restrict__ out)
{
    __shared__ float As[KC][TILE_M + 1];   // [k][m], relu already applied
    __shared__ float Bs[KC][TILE_N];       // [k][n]
    __shared__ float Xs[TILE_M][IDIM + 1]; // input slice for this step
    __shared__ float Ws[IDIM][TILE_N];     // w_ih tile (t-invariant)

    const int tid = threadIdx.x;
    const int tx  = tid & 15;          // 0..15 -> 4 cols each
    const int ty  = tid >> 4;          // 0..15 -> 2 rows each
    const int b0  = (blockIdx.x & 15) * TILE_M;
    const int n0  = (blockIdx.x >> 4) * TILE_N;
    const int r0  = 2 * ty;
    const int c0  = 4 * tx;

    // t-invariant: w_ih tile + bias for this thread's 4 columns
    for (int p = tid; p < IDIM * TILE_N; p += NTHREADS) {
        int i = p >> 6, j = p & 63;
        Ws[i][j] = w_ih[i * HDIM + n0 + j];
    }
    const float4 bias_c = *reinterpret_cast<const float4*>(bias + n0 + c0);
    __syncthreads();

    for (int t = 0; t < T_STEPS; ++t) {
        const float* st = out + (size_t)t * BATCH * HDIM;
        float*       nx = out + (size_t)(t + 1) * BATCH * HDIM;

        float acc[2][4] = {{0.f,0.f,0.f,0.f},{0.f,0.f,0.f,0.f}};

        // ---- main GEMM: relu(state[b0:b0+32, :]) @ wmask[:, n0:n0+64] ----
        for (int k0 = 0; k0 < HDIM; k0 += KC) {
            // A tile: 32 rows x KC k (relu on load, via L2 for coherence)
            for (int p = tid; p < TILE_M * KC / 4; p += NTHREADS) {
                int row = p >> 4;
                int kq  = (p & 15) * 4;
                const float4 v = __ldcg(reinterpret_cast<const float4*>(
                    st + (size_t)(b0 + row) * HDIM + k0 + kq));
                As[kq + 0][row] = fmaxf(v.x, 0.f);
                As[kq + 1][row] = fmaxf(v.y, 0.f);
                As[kq + 2][row] = fmaxf(v.z, 0.f);
                As[kq + 3][row] = fmaxf(v.w, 0.f);
            }
            // B tile: KC x 64 from masked weights (L2-resident)
            for (int p = tid; p < KC * TILE_N / 4; p += NTHREADS) {
                int kk = p >> 4;
                int j4 = (p & 15) * 4;
                *reinterpret_cast<float4*>(&Bs[kk][j4]) =
                    *reinterpret_cast<const float4*>(
                        g_wmask + (size_t)(k0 + kk) * HDIM + n0 + j4);
            }
            __syncthreads();

            #pragma unroll
            for (int kk = 0; kk < KC; ++kk) {
                const float a0 = As[kk][r0];
                const float a1 = As[kk][r0 + 1];
                const float4 b = *reinterpret_cast<const float4*>(&Bs[kk][c0]);
                acc[0][0] += a0 * b.x;  acc[0][1] += a0 * b.y;
                acc[0][2] += a0 * b.z;  acc[0][3] += a0 * b.w;
                acc[1][0] += a1 * b.x;  acc[1][1] += a1 * b.y;
                acc[1][2] += a1 * b.z;  acc[1][3] += a1 * b.w;
            }
            __syncthreads();
        }

        // ---- input projection: x[t, b0:b0+32, :13] @ w_ih[:, n0:n0+64] ----
        for (int p = tid; p < TILE_M * IDIM; p += NTHREADS) {
            int row = p / IDIM, i = p - row * IDIM;
            Xs[row][i] = inputs[(size_t)t * BATCH * IDIM + (size_t)(b0 + row) * IDIM + i];
        }
        __syncthreads();
        #pragma unroll
        for (int i = 0; i < IDIM; ++i) {
            const float x0 = Xs[r0][i];
            const float x1 = Xs[r0 + 1][i];
            const float4 w = *reinterpret_cast<const float4*>(&Ws[i][c0]);
            acc[0][0] += x0 * w.x;  acc[0][1] += x0 * w.y;
            acc[0][2] += x0 * w.z;  acc[0][3] += x0 * w.w;
            acc[1][0] += x1 * w.x;  acc[1][1] += x1 * w.y;
            acc[1][2] += x1 * w.z;  acc[1][3] += x1 * w.w;
        }

        // ---- epilogue: noise, leak, write next state ----
        #pragma unroll
        for (int r = 0; r < 2; ++r) {
            const int b = b0 + r0 + r;
            const size_t off = (size_t)b * HDIM + n0 + c0;
            const float4 nz = __ldg(reinterpret_cast<const float4*>(
                noise + (size_t)t * BATCH * HDIM + off));
            const float4 sv = __ldcg(reinterpret_cast<const float4*>(st + off));
            float4 o;
            o.x = (1.f - ALPHA_C) * sv.x + ALPHA_C * (acc[r][0] + bias_c.x + SIGMA_C * nz.x);
            o.y = (1.f - ALPHA_C) * sv.y + ALPHA_C * (acc[r][1] + bias_c.y + SIGMA_C * nz.y);
            o.z = (1.f - ALPHA_C) * sv.z + ALPHA_C * (acc[r][2] + bias_c.z + SIGMA_C * nz.z);
            o.w = (1.f - ALPHA_C) * sv.w + ALPHA_C * (acc[r][3] + bias_c.w + SIGMA_C * nz.w);
            *reinterpret_cast<float4*>(nx + off) = o;
        }

        // ---- global barrier (skip after final step) ----
        if (t + 1 < T_STEPS) {
            __syncthreads();
            if (tid == 0) {
                __threadfence();                       // release our writes
                atomicAdd(&g_bar, 1u);
                const unsigned target = (unsigned)(t + 1) * gridDim.x;
                unsigned v;
                do {
                    asm volatile("ld.global.acquire.gpu.u32 %0, [%1];"
                                 : "=r"(v) : "l"(&g_bar));
                    if (v >= target) break;
                    __nanosleep(64);
                } while (true);
            }
            __syncthreads();
        }
    }
}

// ---------------------------------------------------------------------------
extern "C" void kernel_launch(void* const* d_in, const int* in_sizes, int n_in,
                              void* d_out, int out_size)
{
    const float* inputs = (const float*)d_in[0];
    const float* init_s = (const float*)d_in[1];
    const float* noise  = (const float*)d_in[2];
    const float* w_ih   = (const float*)d_in[3];
    const float* w_hh   = (const float*)d_in[4];
    const float* bias   = (const float*)d_in[5];
    float* out = (float*)d_out;

    // reset barrier each launch (graph-capturable memset node)
    void* bar_addr = nullptr;
    cudaGetSymbolAddress(&bar_addr, g_bar);
    cudaMemsetAsync(bar_addr, 0, sizeof(unsigned), 0);

    prep_kernel<<<256, 256>>>(w_hh, init_s, out);
    rnn_kernel<<<GRID_X, NTHREADS>>>(inputs, noise, w_ih, bias, out);
}